// round 6
// baseline (speedup 1.0000x reference)
#include <cuda_runtime.h>

#define LAYERS   8
#define WIDTH    128
#define DDIM     64
#define KNOTS    8
#define PPD      23          // 3*KNOTS-1
#define BATCH    16384
#define TB       64          // batch rows per CTA
#define NTHREADS 256
#define DG       16          // dims per chunk (2 per warp)
#define NCHUNK   (DDIM/DG)   // 4
#define WSPAD    68          // padded row stride (floats), conflict-free
#define XPAD     68
#define HPAD     132
#define WSLICE   (16*WSPAD)  // per-warp WS slice (16 rows max)
#define BI       4.0f

// shared memory layout (float offsets)
#define OFF_X0   0
#define OFF_X1   (TB*XPAD)                    // 4352
#define OFF_H    (2*TB*XPAD)                  // 8704
#define OFF_WS   (2*TB*XPAD + TB*HPAD)        // 17152
#define SMEM_FLOATS (OFF_WS + 8*WSLICE)       // 17152 + 8704 = 25856
#define SMEM_BYTES  (SMEM_FLOATS*4)           // 103424 B -> 2 CTAs/SM

// Pre-masked, degree-sorted weights (static device scratch)
__device__ float g_W1m[2*LAYERS*WIDTH*DDIM];
__device__ float g_Wom[2*LAYERS*DDIM*PPD*WIDTH];
__device__ float g_b1p[2*LAYERS*WIDTH];

// ---------------------------------------------------------------------------
// packed fp32x2 FMA: 2 MACs per fma-pipe issue slot
// ---------------------------------------------------------------------------
__device__ __forceinline__ unsigned long long ffma2(unsigned long long a,
                                                    unsigned long long b,
                                                    unsigned long long c)
{
    unsigned long long d;
    asm("fma.rn.f32x2 %0, %1, %2, %3;" : "=l"(d) : "l"(a), "l"(b), "l"(c));
    return d;
}
__device__ __forceinline__ float2 unpack2(unsigned long long v)
{
    float2 r;
    asm("mov.b64 {%0, %1}, %2;" : "=f"(r.x), "=f"(r.y) : "l"(v));
    return r;
}

// ---------------------------------------------------------------------------
// Degree-sorted hidden permutation.
// ---------------------------------------------------------------------------
__host__ __device__ __forceinline__ int sdeg(int j) { return (j < 6) ? (j/3) : ((j-2)>>1); }
__host__ __device__ __forceinline__ int permf(int j)
{
    if (j < 3)  return (j == 0) ? 0 : (j == 1 ? 63 : 126);
    if (j < 6)  return (j == 3) ? 1 : (j == 4 ? 64 : 127);
    int v = (j - 2) >> 1;
    return ((j & 1) == 0) ? v : v + 63;
}
// prefix length of dim d over sorted hidden, rounded up to 8
__device__ __forceinline__ int kmax_of(int d)
{
    int n = (d == 0) ? 0 : (d == 1 ? 3 : 2*d + 2);
    n = (n + 7) & ~7;
    return n > 128 ? 128 : n;
}

// ---------------------------------------------------------------------------
// Prep: mask + permute weights once per launch.
// ---------------------------------------------------------------------------
__global__ void prep_kernel(const float* __restrict__ fW1, const float* __restrict__ fWo,
                            const float* __restrict__ gW1, const float* __restrict__ gWo,
                            const float* __restrict__ fb1, const float* __restrict__ gb1)
{
    const int N1 = LAYERS*WIDTH*DDIM;
    const int N2 = LAYERS*DDIM*PPD*WIDTH;
    const int stride = gridDim.x * blockDim.x;
    const int t0 = blockIdx.x*blockDim.x + threadIdx.x;

    for (int i = t0; i < 2*N1; i += stride) {
        int fl = i / N1, j = i - fl*N1;
        int row = (j >> 6) & (WIDTH-1);
        int c = j & (DDIM-1);
        int l = j >> 13;
        const float* s = fl ? gW1 : fW1;
        int src = permf(row);
        g_W1m[i] = (c <= sdeg(row)) ? s[l*WIDTH*DDIM + src*DDIM + c] : 0.f;
    }
    for (int i = t0; i < 2*N2; i += stride) {
        int fl = i / N2, j = i - fl*N2;
        int col = j & (WIDTH-1);
        int o = (j >> 7) % (DDIM*PPD);
        int l = j / (DDIM*PPD*WIDTH);
        int d = o / PPD;
        const float* s = fl ? gWo : fWo;
        int src = permf(col);
        g_Wom[i] = (sdeg(col) < d) ? s[l*(DDIM*PPD)*WIDTH + o*WIDTH + src] : 0.f;
    }
    for (int i = t0; i < 2*LAYERS*WIDTH; i += stride) {
        int fl = i / (LAYERS*WIDTH), j = i - fl*(LAYERS*WIDTH);
        int l = j >> 7, w = j & (WIDTH-1);
        const float* s = fl ? gb1 : fb1;
        g_b1p[i] = s[l*WIDTH + permf(w)];
    }
}

// ---------------------------------------------------------------------------
// GEMM2 pass, warp-autonomous: stages this warp's 2 dims x PCNT param rows
// into the warp's private WS slice, __syncwarp, FFMA2 K-packed compute.
// out[ri][p] = dot + bias.
// ---------------------------------------------------------------------------
template<int PBASE, int PCNT>
__device__ __forceinline__ void gemm2_pass(
    float* sm, float* ws, const float* __restrict__ Wol, const float* __restrict__ bo,
    int dbase, int rr0, int c4, int dlh, int rg,
    int kmax, int kwmax, float out[4][8])
{
    unsigned long long acc[4][PCNT];
#pragma unroll
    for (int ri = 0; ri < 4; ri++)
#pragma unroll
        for (int p = 0; p < PCNT; p++) acc[ri][p] = 0ull;

    for (int kh = 0; kh < 2; kh++) {
        if (kh*64 >= kwmax) break;                  // warp-uniform
        const int halfK = min(64, kwmax - kh*64);
        const int hk4 = halfK >> 2;
        // stage: rows (dd,pp), lanes: rr0 = row parity, c4 = col
#pragma unroll
        for (int dd = 0; dd < 2; dd++)
#pragma unroll
            for (int ppi = 0; ppi < (PCNT+1)/2; ppi++) {
                int pp = 2*ppi + rr0;
                if (pp < PCNT && c4 < hk4) {
                    float4 v = *(const float4*)&Wol[((dbase+dd)*PPD + PBASE + pp)*WIDTH + kh*64 + c4*4];
                    *(float4*)&ws[(dd*PCNT+pp)*WSPAD + c4*4] = v;
                }
            }
        __syncwarp();

        int bound = kmax - kh*64;
        bound = bound < 0 ? 0 : (bound > halfK ? halfK : bound);
        const float* hbase = &sm[OFF_H + kh*64];
        const float* wsp   = &ws[dlh*PCNT*WSPAD];
#pragma unroll 2
        for (int k4 = 0; k4 < (bound >> 2); k4++) {
            ulonglong2 h0 = *(const ulonglong2*)&hbase[(rg     )*HPAD + k4*4];
            ulonglong2 h1 = *(const ulonglong2*)&hbase[(rg + 16)*HPAD + k4*4];
            ulonglong2 h2 = *(const ulonglong2*)&hbase[(rg + 32)*HPAD + k4*4];
            ulonglong2 h3 = *(const ulonglong2*)&hbase[(rg + 48)*HPAD + k4*4];
#pragma unroll
            for (int p = 0; p < PCNT; p++) {
                ulonglong2 wv = *(const ulonglong2*)&wsp[p*WSPAD + k4*4];
                acc[0][p] = ffma2(h0.x, wv.x, acc[0][p]);
                acc[0][p] = ffma2(h0.y, wv.y, acc[0][p]);
                acc[1][p] = ffma2(h1.x, wv.x, acc[1][p]);
                acc[1][p] = ffma2(h1.y, wv.y, acc[1][p]);
                acc[2][p] = ffma2(h2.x, wv.x, acc[2][p]);
                acc[2][p] = ffma2(h2.y, wv.y, acc[2][p]);
                acc[3][p] = ffma2(h3.x, wv.x, acc[3][p]);
                acc[3][p] = ffma2(h3.y, wv.y, acc[3][p]);
            }
        }
        __syncwarp();   // protect ws before next pass restages
    }

#pragma unroll
    for (int ri = 0; ri < 4; ri++)
#pragma unroll
        for (int p = 0; p < PCNT; p++) {
            float2 u = unpack2(acc[ri][p]);
            out[ri][p] = u.x + u.y + bo[PBASE + p];
        }
}

// ---------------------------------------------------------------------------
// Main kernel: one CTA = 64 rows through all 8 layers; 2 CTAs/SM.
// Only 2 CTA barriers per layer; all staging warp-private.
// ---------------------------------------------------------------------------
__global__ __launch_bounds__(NTHREADS, 2)
void maf_kernel(const float* __restrict__ xin_f, const float* __restrict__ xin_g,
                const float* __restrict__ f_bout, const float* __restrict__ g_bout,
                float* __restrict__ out)
{
    extern __shared__ float sm[];
    const int tid   = threadIdx.x;
    const int flow  = blockIdx.y;
    const int row0  = blockIdx.x * TB;
    const int warpi = tid >> 5;
    const int lane  = tid & 31;
    const int rg    = lane & 15;   // row lane: rows rg + 16*{0..3}
    const int dlh   = lane >> 4;   // 0/1: which of the warp's two dims
    const int dl    = 2*warpi + dlh;   // dim lane within chunk (0..15)
    const int rr0   = dlh;         // staging row parity
    const int c4    = rg;          // staging col (float4 index)

    float* ws = &sm[OFF_WS + warpi*WSLICE];

    const float* xin   = flow ? xin_g  : xin_f;
    const float* boutg = flow ? g_bout : f_bout;
    const float* b1p   = g_b1p + flow * (LAYERS*WIDTH);
    const float* W1m   = g_W1m + flow * (LAYERS*WIDTH*DDIM);
    const float* Wom   = g_Wom + flow * (LAYERS*DDIM*PPD*WIDTH);

    for (int i = tid; i < TB*DDIM; i += NTHREADS) {
        int r = i >> 6, d = i & 63;
        sm[OFF_X0 + r*XPAD + d] = xin[row0*DDIM + i];
    }

    const float C1 = 8.0f / 1.01f;
    const float CADJ = 0.00125f;

    float ldacc[4] = {0.f, 0.f, 0.f, 0.f};
    int cur = OFF_X0, nxt = OFF_X1;

    __syncthreads();

    for (int layer = 0; layer < LAYERS; layer++) {
        // ---- warp-private W1 stage: rows 16*warpi..+16, full 64 cols ----
        {
            const float* W1l = W1m + layer*WIDTH*DDIM + (16*warpi)*DDIM;
#pragma unroll
            for (int rri = 0; rri < 8; rri++) {
                int rr = 2*rri + rr0;
                float4 v = *(const float4*)&W1l[rr*DDIM + c4*4];
                *(float4*)&ws[rr*WSPAD + c4*4] = v;
            }
            __syncwarp();
        }

        // ---- GEMM1: 4 rows x 8 hidden per thread, K-prefix bounded ----
        {
            unsigned long long acc[4][8];
#pragma unroll
            for (int ri = 0; ri < 4; ri++)
#pragma unroll
                for (int p = 0; p < 8; p++) acc[ri][p] = 0ull;

            const float* wsp = &ws[dlh*8*WSPAD];
            const int kb = 2*warpi + dlh + 1;     // k4 iterations (prefix)
#pragma unroll 2
            for (int k4 = 0; k4 < kb; k4++) {
                ulonglong2 x0 = *(const ulonglong2*)&sm[cur + (rg     )*XPAD + k4*4];
                ulonglong2 x1 = *(const ulonglong2*)&sm[cur + (rg + 16)*XPAD + k4*4];
                ulonglong2 x2 = *(const ulonglong2*)&sm[cur + (rg + 32)*XPAD + k4*4];
                ulonglong2 x3 = *(const ulonglong2*)&sm[cur + (rg + 48)*XPAD + k4*4];
#pragma unroll
                for (int p = 0; p < 8; p++) {
                    ulonglong2 wv = *(const ulonglong2*)&wsp[p*WSPAD + k4*4];
                    acc[0][p] = ffma2(x0.x, wv.x, acc[0][p]);
                    acc[0][p] = ffma2(x0.y, wv.y, acc[0][p]);
                    acc[1][p] = ffma2(x1.x, wv.x, acc[1][p]);
                    acc[1][p] = ffma2(x1.y, wv.y, acc[1][p]);
                    acc[2][p] = ffma2(x2.x, wv.x, acc[2][p]);
                    acc[2][p] = ffma2(x2.y, wv.y, acc[2][p]);
                    acc[3][p] = ffma2(x3.x, wv.x, acc[3][p]);
                    acc[3][p] = ffma2(x3.y, wv.y, acc[3][p]);
                }
            }
            const float* bptr = &b1p[layer*WIDTH + dl*8];
            float4 bv0 = *(const float4*)bptr;
            float4 bv1 = *(const float4*)(bptr + 4);
            float b[8] = {bv0.x, bv0.y, bv0.z, bv0.w, bv1.x, bv1.y, bv1.z, bv1.w};
#pragma unroll
            for (int ri = 0; ri < 4; ri++) {
                int r = rg + 16*ri;
                float hv[8];
#pragma unroll
                for (int p = 0; p < 8; p++) {
                    float2 u = unpack2(acc[ri][p]);
                    hv[p] = fmaxf(u.x + u.y + b[p], 0.f);
                }
                *(float4*)&sm[OFF_H + r*HPAD + dl*8]     = make_float4(hv[0],hv[1],hv[2],hv[3]);
                *(float4*)&sm[OFF_H + r*HPAD + dl*8 + 4] = make_float4(hv[4],hv[5],hv[6],hv[7]);
            }
        }
        __syncthreads();   // H ready (CTA barrier 1)

        // ---- GEMM2 + streamed spline over 4 chunks of 16 dims ----
        for (int chunk = 0; chunk < NCHUNK; chunk++) {
            const int d0 = chunk * DG;
            const int d  = d0 + dl;
            const int dbase = d0 + 2*warpi;
            const int kmax  = kmax_of(d);
            const int kwmax = kmax_of(dbase + 1);   // warp's larger prefix
            const float* Wol = Wom + layer*DDIM*PPD*WIDTH;
            const float* bo  = boutg + (layer*DDIM + d)*PPD;

            float pr[4][8];
            float st_xraw[4], st_xi[4], st_invdx[4], st_yk[4], st_dyv[4], st_sk[4];
            int   st_k[4];

            // ===== phase 1: widths -> bin index, xi, invdx =====
            gemm2_pass<0, 8>(sm, ws, Wol, bo, dbase, rr0, c4, dlh, rg, kmax, kwmax, pr);
#pragma unroll
            for (int ri = 0; ri < 4; ri++) {
                float mw = pr[ri][0];
#pragma unroll
                for (int j = 1; j < 8; j++) mw = fmaxf(mw, pr[ri][j]);
                float ew[8]; float swv = 0.f;
#pragma unroll
                for (int j = 0; j < 8; j++) { ew[j] = __expf(pr[ri][j] - mw); swv += ew[j]; }
                float isw = __frcp_rn(swv);

                float xraw = sm[cur + (rg + 16*ri)*XPAD + d];
                float xc = fminf(fmaxf(xraw, -BI), BI);

                float xl = -BI;
                float xk = 0.f, xk1 = 1.f;
                int k = 7; bool found = false;
#pragma unroll
                for (int j = 0; j < 8; j++) {
                    float wj = (ew[j]*isw + CADJ) * C1;
                    float xr2 = xl + wj;
                    bool sel = (!found) && ((xc < xr2) || (j == 7));
                    if (sel) { k = j; xk = xl; xk1 = xr2; found = true; }
                    xl = xr2;
                }
                float invdx = __frcp_rn(xk1 - xk);
                st_xraw[ri] = xraw;
                st_invdx[ri] = invdx;
                st_xi[ri] = (xc - xk) * invdx;
                st_k[ri] = k;
            }

            // ===== phase 2: heights -> yk, dyv, sk =====
            gemm2_pass<8, 8>(sm, ws, Wol, bo, dbase, rr0, c4, dlh, rg, kmax, kwmax, pr);
#pragma unroll
            for (int ri = 0; ri < 4; ri++) {
                float mh = pr[ri][0];
#pragma unroll
                for (int j = 1; j < 8; j++) mh = fmaxf(mh, pr[ri][j]);
                float eh[8]; float shv = 0.f;
#pragma unroll
                for (int j = 0; j < 8; j++) { eh[j] = __expf(pr[ri][j] - mh); shv += eh[j]; }
                float ish = __frcp_rn(shv);

                const int k = st_k[ri];
                float yl = -BI;
                float yk = 0.f, yk1 = 1.f;
#pragma unroll
                for (int j = 0; j < 8; j++) {
                    float hj = (eh[j]*ish + CADJ) * C1;
                    float yr2 = yl + hj;
                    if (j == k) { yk = yl; yk1 = yr2; }
                    yl = yr2;
                }
                st_yk[ri] = yk;
                st_dyv[ri] = yk1 - yk;
                st_sk[ri] = st_dyv[ri] * st_invdx[ri];
            }

            // ===== phase 3: derivatives -> finish spline =====
            gemm2_pass<16, 7>(sm, ws, Wol, bo, dbase, rr0, c4, dlh, rg, kmax, kwmax, pr);
#pragma unroll
            for (int ri = 0; ri < 4; ri++) {
                const int k = st_k[ri];
                float dk = 1.f, dk1 = 1.f;
#pragma unroll
                for (int j = 0; j < 7; j++) {
                    float v = pr[ri][j];
                    float sp = (v > 15.f) ? v : log1pf(__expf(v));
                    float sdv = sp + 0.001f;
                    if (j == k - 1) dk  = sdv;
                    if (j == k)     dk1 = sdv;
                }
                float xi = st_xi[ri];
                float omx = 1.f - xi;
                float xiomx = xi * omx;
                float sk = st_sk[ri];
                float den = sk + (dk1 + dk - 2.f*sk) * xiomx;
                float invden = __frcp_rn(den);
                float nume = sk*xi*xi + dk*xiomx;
                float outv = st_yk[ri] + st_dyv[ri] * nume * invden;
                float ldn = dk1*xi*xi + 2.f*sk*xiomx + dk*omx*omx;
                float ld = 2.f*__logf(sk) + __logf(ldn) - 2.f*__logf(den);

                float xraw = st_xraw[ri];
                bool inside = (xraw > -BI) && (xraw < BI);
                float xo2 = inside ? outv : xraw;
                sm[nxt + (rg + 16*ri)*XPAD + (DDIM-1 - d)] = xo2;  // reversal fused
                ldacc[ri] += inside ? ld : 0.f;
            }
        }

        __syncthreads();   // X(nxt) ready (CTA barrier 2)
        int t = cur; cur = nxt; nxt = t;
    }

    // ---- outputs: [xo (B*64) | ldf (B) | yo (B*64) | ldg (B)]
    const int xbase  = flow ? (BATCH*DDIM + BATCH) : 0;
    const int ldbase = flow ? (2*BATCH*DDIM + BATCH) : (BATCH*DDIM);

    for (int i = tid; i < TB*DDIM; i += NTHREADS) {
        int rr = i >> 6, dd = i & 63;
        out[xbase + row0*DDIM + i] = sm[cur + rr*XPAD + dd];
    }

    // log-det reduction: 16 dim-class partials per row
    float* red = &sm[OFF_WS];
#pragma unroll
    for (int ri = 0; ri < 4; ri++)
        red[(rg + 16*ri)*16 + dl] = ldacc[ri];
    __syncthreads();
    if (tid < TB) {
        float s = 0.f;
#pragma unroll
        for (int j = 0; j < 16; j++) s += red[tid*16 + j];
        out[ldbase + row0 + tid] = s;
    }
}

// ---------------------------------------------------------------------------
extern "C" void kernel_launch(void* const* d_in, const int* in_sizes, int n_in,
                              void* d_out, int out_size)
{
    const float* x      = (const float*)d_in[0];
    const float* y      = (const float*)d_in[1];
    const float* f_W1   = (const float*)d_in[2];
    const float* f_b1   = (const float*)d_in[3];
    const float* f_Wout = (const float*)d_in[4];
    const float* f_bout = (const float*)d_in[5];
    const float* g_W1   = (const float*)d_in[6];
    const float* g_b1   = (const float*)d_in[7];
    const float* g_Wout = (const float*)d_in[8];
    const float* g_bout = (const float*)d_in[9];
    float* out = (float*)d_out;

    cudaFuncSetAttribute(maf_kernel, cudaFuncAttributeMaxDynamicSharedMemorySize, SMEM_BYTES);

    prep_kernel<<<1024, 256>>>(f_W1, f_Wout, g_W1, g_Wout, f_b1, g_b1);

    dim3 grid(BATCH/TB, 2);
    maf_kernel<<<grid, NTHREADS, SMEM_BYTES>>>(x, y, f_bout, g_bout, out);
}

// round 7
// speedup vs baseline: 1.0647x; 1.0647x over previous
#include <cuda_runtime.h>

#define LAYERS   8
#define WIDTH    128
#define DDIM     64
#define KNOTS    8
#define PPD      23          // 3*KNOTS-1
#define BATCH    16384
#define TB       64          // batch rows per CTA
#define NTHREADS 512
#define DG       16          // dims per chunk (1 per warp)
#define NCHUNK   (DDIM/DG)   // 4
#define WSPAD    68          // padded row stride (floats), conflict-free
#define XPAD     68
#define HPAD     132
#define BI       4.0f

// shared memory layout (float offsets)
#define OFF_X0   0
#define OFF_X1   (TB*XPAD)                    // 4352
#define OFF_H    (2*TB*XPAD)                  // 8704
#define OFF_WS   (2*TB*XPAD + TB*HPAD)        // 17152
#define SMEM_FLOATS (OFF_WS + 128*WSPAD)      // 17152 + 8704 = 25856
#define SMEM_BYTES  (SMEM_FLOATS*4)           // 103424 B -> 2 CTAs/SM

// Pre-masked, degree-sorted weights (static device scratch)
__device__ float g_W1m[2*LAYERS*WIDTH*DDIM];
__device__ float g_Wom[2*LAYERS*DDIM*PPD*WIDTH];
__device__ float g_b1p[2*LAYERS*WIDTH];

// ---------------------------------------------------------------------------
// packed fp32x2 FMA: 2 MACs per fma-pipe issue slot
// ---------------------------------------------------------------------------
__device__ __forceinline__ unsigned long long ffma2(unsigned long long a,
                                                    unsigned long long b,
                                                    unsigned long long c)
{
    unsigned long long d;
    asm("fma.rn.f32x2 %0, %1, %2, %3;" : "=l"(d) : "l"(a), "l"(b), "l"(c));
    return d;
}
__device__ __forceinline__ float2 unpack2(unsigned long long v)
{
    float2 r;
    asm("mov.b64 {%0, %1}, %2;" : "=f"(r.x), "=f"(r.y) : "l"(v));
    return r;
}

// ---------------------------------------------------------------------------
// Degree-sorted hidden permutation.
// ---------------------------------------------------------------------------
__host__ __device__ __forceinline__ int sdeg(int j) { return (j < 6) ? (j/3) : ((j-2)>>1); }
__host__ __device__ __forceinline__ int permf(int j)
{
    if (j < 3)  return (j == 0) ? 0 : (j == 1 ? 63 : 126);
    if (j < 6)  return (j == 3) ? 1 : (j == 4 ? 64 : 127);
    int v = (j - 2) >> 1;
    return ((j & 1) == 0) ? v : v + 63;
}
// prefix length of dim d over sorted hidden, rounded up to 8
__device__ __forceinline__ int kmax_of(int d)
{
    int n = (d == 0) ? 0 : (d == 1 ? 3 : 2*d + 2);
    n = (n + 7) & ~7;
    return n > 128 ? 128 : n;
}

// ---------------------------------------------------------------------------
// Prep: mask + permute weights once per launch.
// ---------------------------------------------------------------------------
__global__ void prep_kernel(const float* __restrict__ fW1, const float* __restrict__ fWo,
                            const float* __restrict__ gW1, const float* __restrict__ gWo,
                            const float* __restrict__ fb1, const float* __restrict__ gb1)
{
    const int N1 = LAYERS*WIDTH*DDIM;
    const int N2 = LAYERS*DDIM*PPD*WIDTH;
    const int stride = gridDim.x * blockDim.x;
    const int t0 = blockIdx.x*blockDim.x + threadIdx.x;

    for (int i = t0; i < 2*N1; i += stride) {
        int fl = i / N1, j = i - fl*N1;
        int row = (j >> 6) & (WIDTH-1);
        int c = j & (DDIM-1);
        int l = j >> 13;
        const float* s = fl ? gW1 : fW1;
        int src = permf(row);
        g_W1m[i] = (c <= sdeg(row)) ? s[l*WIDTH*DDIM + src*DDIM + c] : 0.f;
    }
    for (int i = t0; i < 2*N2; i += stride) {
        int fl = i / N2, j = i - fl*N2;
        int col = j & (WIDTH-1);
        int o = (j >> 7) % (DDIM*PPD);
        int l = j / (DDIM*PPD*WIDTH);
        int d = o / PPD;
        const float* s = fl ? gWo : fWo;
        int src = permf(col);
        g_Wom[i] = (sdeg(col) < d) ? s[l*(DDIM*PPD)*WIDTH + o*WIDTH + src] : 0.f;
    }
    for (int i = t0; i < 2*LAYERS*WIDTH; i += stride) {
        int fl = i / (LAYERS*WIDTH), j = i - fl*(LAYERS*WIDTH);
        int l = j >> 7, w = j & (WIDTH-1);
        const float* s = fl ? gb1 : fb1;
        g_b1p[i] = s[l*WIDTH + permf(w)];
    }
}

// ---------------------------------------------------------------------------
// GEMM2 pass: PCNT params x 2 rows over this warp's dim K-prefix.
// CTA-wide staging; warp-uniform compute bound; FFMA2 K-packed.
// ---------------------------------------------------------------------------
template<int PBASE, int PCNT>
__device__ __forceinline__ void gemm2_pass(
    float* sm, const float* __restrict__ Wol, const float* __restrict__ bo,
    int d0, int dl, int lane, int chunkK, int kmax, float out[2][8])
{
    unsigned long long acc[2][PCNT];
#pragma unroll
    for (int ri = 0; ri < 2; ri++)
#pragma unroll
        for (int p = 0; p < PCNT; p++) acc[ri][p] = 0ull;

    for (int kh = 0; kh < 2; kh++) {
        if (kh*64 >= chunkK) break;                 // CTA-uniform
        const int halfK = min(64, chunkK - kh*64);
        const int hk4 = halfK >> 2;
        const int shf = (hk4 == 8) ? 3 : 4;
        // CTA-wide stage: DG*PCNT rows x halfK cols
        for (int i = threadIdx.x; i < DG*PCNT*hk4; i += NTHREADS) {
            int rr = i >> shf, c4 = i & (hk4 - 1);
            int dd = rr / PCNT, pp = rr - dd*PCNT;
            float4 v = *(const float4*)&Wol[((d0+dd)*PPD + PBASE + pp)*WIDTH + kh*64 + c4*4];
            *(float4*)&sm[OFF_WS + rr*WSPAD + c4*4] = v;
        }
        __syncthreads();

        int bound = kmax - kh*64;                   // warp-uniform
        bound = bound < 0 ? 0 : (bound > halfK ? halfK : bound);
        const float* hbase = &sm[OFF_H + kh*64];
        const float* wsp   = &sm[OFF_WS + (dl*PCNT)*WSPAD];
#pragma unroll 4
        for (int k4 = 0; k4 < (bound >> 2); k4++) {
            ulonglong2 h0 = *(const ulonglong2*)&hbase[(lane     )*HPAD + k4*4];
            ulonglong2 h1 = *(const ulonglong2*)&hbase[(lane + 32)*HPAD + k4*4];
#pragma unroll
            for (int p = 0; p < PCNT; p++) {
                ulonglong2 wv = *(const ulonglong2*)&wsp[p*WSPAD + k4*4];
                acc[0][p] = ffma2(h0.x, wv.x, acc[0][p]);
                acc[0][p] = ffma2(h0.y, wv.y, acc[0][p]);
                acc[1][p] = ffma2(h1.x, wv.x, acc[1][p]);
                acc[1][p] = ffma2(h1.y, wv.y, acc[1][p]);
            }
        }
        __syncthreads();
    }

#pragma unroll
    for (int ri = 0; ri < 2; ri++)
#pragma unroll
        for (int p = 0; p < PCNT; p++) {
            float2 u = unpack2(acc[ri][p]);
            out[ri][p] = u.x + u.y + bo[PBASE + p];
        }
}

// ---------------------------------------------------------------------------
// Main kernel: one CTA (512 thr) = 64 rows through all 8 layers; 2 CTAs/SM.
// Warp w owns dim d0+w (GEMM2) / hidden octet 8w (GEMM1); lane owns rows
// {lane, lane+32}.  Spline streamed in 3 phases.
// ---------------------------------------------------------------------------
__global__ __launch_bounds__(NTHREADS, 2)
void maf_kernel(const float* __restrict__ xin_f, const float* __restrict__ xin_g,
                const float* __restrict__ f_bout, const float* __restrict__ g_bout,
                float* __restrict__ out)
{
    extern __shared__ float sm[];
    const int tid   = threadIdx.x;
    const int flow  = blockIdx.y;
    const int row0  = blockIdx.x * TB;
    const int warpi = tid >> 5;    // 0..15
    const int lane  = tid & 31;
    const int dl    = warpi;       // dim lane within chunk

    const float* xin   = flow ? xin_g  : xin_f;
    const float* boutg = flow ? g_bout : f_bout;
    const float* b1p   = g_b1p + flow * (LAYERS*WIDTH);
    const float* W1m   = g_W1m + flow * (LAYERS*WIDTH*DDIM);
    const float* Wom   = g_Wom + flow * (LAYERS*DDIM*PPD*WIDTH);

    for (int i = tid; i < TB*DDIM; i += NTHREADS) {
        int r = i >> 6, d = i & 63;
        sm[OFF_X0 + r*XPAD + d] = xin[row0*DDIM + i];
    }

    const float C1 = 8.0f / 1.01f;
    const float CADJ = 0.00125f;

    float ldacc[2] = {0.f, 0.f};
    int cur = OFF_X0, nxt = OFF_X1;

    __syncthreads();

    for (int layer = 0; layer < LAYERS; layer++) {
        // ---- CTA-wide W1 stage: 128 rows x 64 cols ----
        const float* W1l = W1m + layer*WIDTH*DDIM;
        for (int i = tid; i < WIDTH*DDIM/4; i += NTHREADS) {
            int w = i >> 4, c4 = i & 15;
            float4 v = ((const float4*)W1l)[i];
            *(float4*)&sm[OFF_WS + w*WSPAD + c4*4] = v;
        }
        __syncthreads();

        // ---- GEMM1: warp w -> hidden 8w..8w+8; lane -> rows {lane, lane+32}
        {
            unsigned long long acc[2][8];
#pragma unroll
            for (int ri = 0; ri < 2; ri++)
#pragma unroll
                for (int p = 0; p < 8; p++) acc[ri][p] = 0ull;

            const float* wsp = &sm[OFF_WS + (warpi*8)*WSPAD];
            const int kb = warpi + 1;       // k4 iterations (prefix of octet)
#pragma unroll 4
            for (int k4 = 0; k4 < kb; k4++) {
                ulonglong2 x0 = *(const ulonglong2*)&sm[cur + (lane     )*XPAD + k4*4];
                ulonglong2 x1 = *(const ulonglong2*)&sm[cur + (lane + 32)*XPAD + k4*4];
#pragma unroll
                for (int p = 0; p < 8; p++) {
                    ulonglong2 wv = *(const ulonglong2*)&wsp[p*WSPAD + k4*4];
                    acc[0][p] = ffma2(x0.x, wv.x, acc[0][p]);
                    acc[0][p] = ffma2(x0.y, wv.y, acc[0][p]);
                    acc[1][p] = ffma2(x1.x, wv.x, acc[1][p]);
                    acc[1][p] = ffma2(x1.y, wv.y, acc[1][p]);
                }
            }
            const float* bptr = &b1p[layer*WIDTH + warpi*8];
            float4 bv0 = *(const float4*)bptr;
            float4 bv1 = *(const float4*)(bptr + 4);
            float b[8] = {bv0.x, bv0.y, bv0.z, bv0.w, bv1.x, bv1.y, bv1.z, bv1.w};
#pragma unroll
            for (int ri = 0; ri < 2; ri++) {
                int r = lane + 32*ri;
                float hv[8];
#pragma unroll
                for (int p = 0; p < 8; p++) {
                    float2 u = unpack2(acc[ri][p]);
                    hv[p] = fmaxf(u.x + u.y + b[p], 0.f);
                }
                *(float4*)&sm[OFF_H + r*HPAD + warpi*8]     = make_float4(hv[0],hv[1],hv[2],hv[3]);
                *(float4*)&sm[OFF_H + r*HPAD + warpi*8 + 4] = make_float4(hv[4],hv[5],hv[6],hv[7]);
            }
        }
        __syncthreads();   // H ready

        // ---- GEMM2 + streamed spline over 4 chunks of 16 dims ----
        for (int chunk = 0; chunk < NCHUNK; chunk++) {
            const int d0 = chunk * DG;
            const int d  = d0 + dl;
            const int kmax   = kmax_of(d);              // warp-uniform
            const int chunkK = kmax_of(d0 + 15);        // CTA-uniform
            const float* Wol = Wom + layer*DDIM*PPD*WIDTH;
            const float* bo  = boutg + (layer*DDIM + d)*PPD;

            float pr[2][8];
            float st_xi[2], st_invdx[2], st_yk[2], st_dyv[2], st_sk[2];
            int   st_k[2];

            // ===== phase 1: widths -> bin index, xi, invdx =====
            gemm2_pass<0, 8>(sm, Wol, bo, d0, dl, lane, chunkK, kmax, pr);
#pragma unroll
            for (int ri = 0; ri < 2; ri++) {
                float mw = pr[ri][0];
#pragma unroll
                for (int j = 1; j < 8; j++) mw = fmaxf(mw, pr[ri][j]);
                float ew[8]; float swv = 0.f;
#pragma unroll
                for (int j = 0; j < 8; j++) { ew[j] = __expf(pr[ri][j] - mw); swv += ew[j]; }
                float isw = __frcp_rn(swv);

                float xraw = sm[cur + (lane + 32*ri)*XPAD + d];
                float xc = fminf(fmaxf(xraw, -BI), BI);

                // running-update bin search: last j with xc >= left edge
                float xl = -BI;
                float xk = -BI, xk1 = -BI;
                int k = 0;
#pragma unroll
                for (int j = 0; j < 8; j++) {
                    float wj = (ew[j]*isw + CADJ) * C1;
                    float xr2 = xl + wj;
                    if (xc >= xl) { k = j; xk = xl; xk1 = xr2; }
                    xl = xr2;
                }
                float invdx = __frcp_rn(xk1 - xk);
                st_invdx[ri] = invdx;
                st_xi[ri] = (xc - xk) * invdx;
                st_k[ri] = k;
            }

            // ===== phase 2: heights -> yk, dyv, sk =====
            gemm2_pass<8, 8>(sm, Wol, bo, d0, dl, lane, chunkK, kmax, pr);
#pragma unroll
            for (int ri = 0; ri < 2; ri++) {
                float mh = pr[ri][0];
#pragma unroll
                for (int j = 1; j < 8; j++) mh = fmaxf(mh, pr[ri][j]);
                float eh[8]; float shv = 0.f;
#pragma unroll
                for (int j = 0; j < 8; j++) { eh[j] = __expf(pr[ri][j] - mh); shv += eh[j]; }
                float ish = __frcp_rn(shv);

                const int k = st_k[ri];
                float yl = -BI;
                float yk = -BI, yk1 = -BI;
#pragma unroll
                for (int j = 0; j < 8; j++) {
                    float hj = (eh[j]*ish + CADJ) * C1;
                    float yr2 = yl + hj;
                    if (j == k) { yk = yl; yk1 = yr2; }
                    yl = yr2;
                }
                st_yk[ri] = yk;
                st_dyv[ri] = yk1 - yk;
                st_sk[ri] = st_dyv[ri] * st_invdx[ri];
            }

            // ===== phase 3: derivatives -> finish spline =====
            gemm2_pass<16, 7>(sm, Wol, bo, d0, dl, lane, chunkK, kmax, pr);
#pragma unroll
            for (int ri = 0; ri < 2; ri++) {
                const int k = st_k[ri];
                float dk = 1.f, dk1 = 1.f;
#pragma unroll
                for (int j = 0; j < 7; j++) {
                    float v = pr[ri][j];
                    float sp = (v > 15.f) ? v : log1pf(__expf(v));
                    float sdv = sp + 0.001f;
                    if (j == k - 1) dk  = sdv;
                    if (j == k)     dk1 = sdv;
                }
                float xi = st_xi[ri];
                float omx = 1.f - xi;
                float xiomx = xi * omx;
                float sk = st_sk[ri];
                float den = sk + (dk1 + dk - 2.f*sk) * xiomx;
                float invden = __frcp_rn(den);
                float nume = sk*xi*xi + dk*xiomx;
                float outv = st_yk[ri] + st_dyv[ri] * nume * invden;
                float ldn = dk1*xi*xi + 2.f*sk*xiomx + dk*omx*omx;
                float ld = 2.f*__logf(sk) + __logf(ldn) - 2.f*__logf(den);

                float xraw = sm[cur + (lane + 32*ri)*XPAD + d];
                bool inside = (xraw > -BI) && (xraw < BI);
                float xo2 = inside ? outv : xraw;
                sm[nxt + (lane + 32*ri)*XPAD + (DDIM-1 - d)] = xo2;  // reversal fused
                ldacc[ri] += inside ? ld : 0.f;
            }
        }

        __syncthreads();   // X(nxt) ready
        int t = cur; cur = nxt; nxt = t;
    }

    // ---- outputs: [xo (B*64) | ldf (B) | yo (B*64) | ldg (B)]
    const int xbase  = flow ? (BATCH*DDIM + BATCH) : 0;
    const int ldbase = flow ? (2*BATCH*DDIM + BATCH) : (BATCH*DDIM);

    for (int i = tid; i < TB*DDIM; i += NTHREADS) {
        int rr = i >> 6, dd = i & 63;
        out[xbase + row0*DDIM + i] = sm[cur + rr*XPAD + dd];
    }

    // log-det reduction: 16 dim-class partials per row
    float* red = &sm[OFF_WS];
#pragma unroll
    for (int ri = 0; ri < 2; ri++)
        red[(lane + 32*ri)*16 + dl] = ldacc[ri];
    __syncthreads();
    if (tid < TB) {
        float s = 0.f;
#pragma unroll
        for (int j = 0; j < 16; j++) s += red[tid*16 + j];
        out[ldbase + row0 + tid] = s;
    }
}

// ---------------------------------------------------------------------------
extern "C" void kernel_launch(void* const* d_in, const int* in_sizes, int n_in,
                              void* d_out, int out_size)
{
    const float* x      = (const float*)d_in[0];
    const float* y      = (const float*)d_in[1];
    const float* f_W1   = (const float*)d_in[2];
    const float* f_b1   = (const float*)d_in[3];
    const float* f_Wout = (const float*)d_in[4];
    const float* f_bout = (const float*)d_in[5];
    const float* g_W1   = (const float*)d_in[6];
    const float* g_b1   = (const float*)d_in[7];
    const float* g_Wout = (const float*)d_in[8];
    const float* g_bout = (const float*)d_in[9];
    float* out = (float*)d_out;

    cudaFuncSetAttribute(maf_kernel, cudaFuncAttributeMaxDynamicSharedMemorySize, SMEM_BYTES);

    prep_kernel<<<1024, 256>>>(f_W1, f_Wout, g_W1, g_Wout, f_b1, g_b1);

    dim3 grid(BATCH/TB, 2);
    maf_kernel<<<grid, NTHREADS, SMEM_BYTES>>>(x, y, f_bout, g_bout, out);
}

// round 9
// speedup vs baseline: 1.1236x; 1.0553x over previous
#include <cuda_runtime.h>

#define LAYERS   8
#define WIDTH    128
#define DDIM     64
#define KNOTS    8
#define PPD      23          // 3*KNOTS-1
#define BATCH    16384
#define TB       64          // batch rows per CTA
#define NTHREADS 512
#define DG       16          // dims per chunk (1 per warp)
#define NCHUNK   (DDIM/DG)   // 4
#define WSPAD    68          // padded row stride (floats), conflict-free
#define XPAD     68
#define HPAD     132
#define BI       4.0f

// shared memory layout (float offsets)
#define OFF_X0   0
#define OFF_X1   (TB*XPAD)                    // 4352
#define OFF_H    (2*TB*XPAD)                  // 8704
#define OFF_WS   (2*TB*XPAD + TB*HPAD)        // 17152
#define SMEM_FLOATS (OFF_WS + 128*WSPAD)      // 17152 + 8704 = 25856
#define SMEM_BYTES  (SMEM_FLOATS*4)           // 103424 B -> 2 CTAs/SM

// Pre-masked, degree-sorted weights (static device scratch)
__device__ float g_W1m[2*LAYERS*WIDTH*DDIM];
__device__ float g_Wom[2*LAYERS*DDIM*PPD*WIDTH];
__device__ float g_b1p[2*LAYERS*WIDTH];

// ---------------------------------------------------------------------------
// packed fp32x2 FMA: 2 MACs per fma-pipe issue slot
// ---------------------------------------------------------------------------
__device__ __forceinline__ unsigned long long ffma2(unsigned long long a,
                                                    unsigned long long b,
                                                    unsigned long long c)
{
    unsigned long long d;
    asm("fma.rn.f32x2 %0, %1, %2, %3;" : "=l"(d) : "l"(a), "l"(b), "l"(c));
    return d;
}
__device__ __forceinline__ float2 unpack2(unsigned long long v)
{
    float2 r;
    asm("mov.b64 {%0, %1}, %2;" : "=f"(r.x), "=f"(r.y) : "l"(v));
    return r;
}

// softplus = max(v,0) + log(1 + exp(-|v|))   (2 MUFU, no library tail)
__device__ __forceinline__ float softplus_fast(float v)
{
    float t = __expf(-fabsf(v));
    return fmaxf(v, 0.f) + __logf(1.f + t);
}

// ---------------------------------------------------------------------------
// Degree-sorted hidden permutation.
// ---------------------------------------------------------------------------
__host__ __device__ __forceinline__ int sdeg(int j) { return (j < 6) ? (j/3) : ((j-2)>>1); }
__host__ __device__ __forceinline__ int permf(int j)
{
    if (j < 3)  return (j == 0) ? 0 : (j == 1 ? 63 : 126);
    if (j < 6)  return (j == 3) ? 1 : (j == 4 ? 64 : 127);
    int v = (j - 2) >> 1;
    return ((j & 1) == 0) ? v : v + 63;
}
// prefix length of dim d over sorted hidden, rounded up to 8
__device__ __forceinline__ int kmax_of(int d)
{
    int n = (d == 0) ? 0 : (d == 1 ? 3 : 2*d + 2);
    n = (n + 7) & ~7;
    return n > 128 ? 128 : n;
}

// ---------------------------------------------------------------------------
// Prep: mask + permute weights once per launch.
// ---------------------------------------------------------------------------
__global__ void prep_kernel(const float* __restrict__ fW1, const float* __restrict__ fWo,
                            const float* __restrict__ gW1, const float* __restrict__ gWo,
                            const float* __restrict__ fb1, const float* __restrict__ gb1)
{
    const int N1 = LAYERS*WIDTH*DDIM;
    const int N2 = LAYERS*DDIM*PPD*WIDTH;
    const int stride = gridDim.x * blockDim.x;
    const int t0 = blockIdx.x*blockDim.x + threadIdx.x;

    for (int i = t0; i < 2*N1; i += stride) {
        int fl = i / N1, j = i - fl*N1;
        int row = (j >> 6) & (WIDTH-1);
        int c = j & (DDIM-1);
        int l = j >> 13;
        const float* s = fl ? gW1 : fW1;
        int src = permf(row);
        g_W1m[i] = (c <= sdeg(row)) ? s[l*WIDTH*DDIM + src*DDIM + c] : 0.f;
    }
    for (int i = t0; i < 2*N2; i += stride) {
        int fl = i / N2, j = i - fl*N2;
        int col = j & (WIDTH-1);
        int o = (j >> 7) % (DDIM*PPD);
        int l = j / (DDIM*PPD*WIDTH);
        int d = o / PPD;
        const float* s = fl ? gWo : fWo;
        int src = permf(col);
        g_Wom[i] = (sdeg(col) < d) ? s[l*(DDIM*PPD)*WIDTH + o*WIDTH + src] : 0.f;
    }
    for (int i = t0; i < 2*LAYERS*WIDTH; i += stride) {
        int fl = i / (LAYERS*WIDTH), j = i - fl*(LAYERS*WIDTH);
        int l = j >> 7, w = j & (WIDTH-1);
        const float* s = fl ? gb1 : fb1;
        g_b1p[i] = s[l*WIDTH + permf(w)];
    }
}

// ---------------------------------------------------------------------------
// GEMM2 pass: PCNT params x 2 rows over this warp's dim K-prefix.
// CTA-wide staging; warp-uniform compute bound; FFMA2 K-packed.
// ---------------------------------------------------------------------------
template<int PBASE, int PCNT>
__device__ __forceinline__ void gemm2_pass(
    float* sm, const float* __restrict__ Wol, const float* __restrict__ bo,
    int d0, int dl, int lane, int chunkK, int kmax, float out[2][8])
{
    unsigned long long acc[2][PCNT];
#pragma unroll
    for (int ri = 0; ri < 2; ri++)
#pragma unroll
        for (int p = 0; p < PCNT; p++) acc[ri][p] = 0ull;

    for (int kh = 0; kh < 2; kh++) {
        if (kh*64 >= chunkK) break;                 // CTA-uniform
        const int halfK = min(64, chunkK - kh*64);
        const int hk4 = halfK >> 2;
        const int shf = (hk4 == 8) ? 3 : 4;
        // CTA-wide stage: DG*PCNT rows x halfK cols
        for (int i = threadIdx.x; i < DG*PCNT*hk4; i += NTHREADS) {
            int rr = i >> shf, c4 = i & (hk4 - 1);
            int dd = rr / PCNT, pp = rr - dd*PCNT;
            float4 v = *(const float4*)&Wol[((d0+dd)*PPD + PBASE + pp)*WIDTH + kh*64 + c4*4];
            *(float4*)&sm[OFF_WS + rr*WSPAD + c4*4] = v;
        }
        __syncthreads();

        int bound = kmax - kh*64;                   // warp-uniform
        bound = bound < 0 ? 0 : (bound > halfK ? halfK : bound);
        const float* hbase = &sm[OFF_H + kh*64];
        const float* wsp   = &sm[OFF_WS + (dl*PCNT)*WSPAD];
#pragma unroll 4
        for (int k4 = 0; k4 < (bound >> 2); k4++) {
            ulonglong2 h0 = *(const ulonglong2*)&hbase[(lane     )*HPAD + k4*4];
            ulonglong2 h1 = *(const ulonglong2*)&hbase[(lane + 32)*HPAD + k4*4];
#pragma unroll
            for (int p = 0; p < PCNT; p++) {
                ulonglong2 wv = *(const ulonglong2*)&wsp[p*WSPAD + k4*4];
                acc[0][p] = ffma2(h0.x, wv.x, acc[0][p]);
                acc[0][p] = ffma2(h0.y, wv.y, acc[0][p]);
                acc[1][p] = ffma2(h1.x, wv.x, acc[1][p]);
                acc[1][p] = ffma2(h1.y, wv.y, acc[1][p]);
            }
        }
        __syncthreads();
    }

#pragma unroll
    for (int ri = 0; ri < 2; ri++)
#pragma unroll
        for (int p = 0; p < PCNT; p++) {
            float2 u = unpack2(acc[ri][p]);
            out[ri][p] = u.x + u.y + bo[PBASE + p];
        }
}

// ---------------------------------------------------------------------------
// Main kernel: one CTA (512 thr) = 64 rows through all 8 layers; 2 CTAs/SM.
// Warp w owns dim d0+w (GEMM2) / hidden octet 8w (GEMM1); lane owns rows
// {lane, lane+32}.  Spline streamed in 3 phases; MUFU-minimized.
// ---------------------------------------------------------------------------
__global__ __launch_bounds__(NTHREADS, 2)
void maf_kernel(const float* __restrict__ xin_f, const float* __restrict__ xin_g,
                const float* __restrict__ f_bout, const float* __restrict__ g_bout,
                float* __restrict__ out)
{
    extern __shared__ float sm[];
    const int tid   = threadIdx.x;
    const int flow  = blockIdx.y;
    const int row0  = blockIdx.x * TB;
    const int warpi = tid >> 5;    // 0..15
    const int lane  = tid & 31;
    const int dl    = warpi;       // dim lane within chunk

    const float* xin   = flow ? xin_g  : xin_f;
    const float* boutg = flow ? g_bout : f_bout;
    const float* b1p   = g_b1p + flow * (LAYERS*WIDTH);
    const float* W1m   = g_W1m + flow * (LAYERS*WIDTH*DDIM);
    const float* Wom   = g_Wom + flow * (LAYERS*DDIM*PPD*WIDTH);

    for (int i = tid; i < TB*DDIM; i += NTHREADS) {
        int r = i >> 6, d = i & 63;
        sm[OFF_X0 + r*XPAD + d] = xin[row0*DDIM + i];
    }

    const float C1 = 8.0f / 1.01f;
    const float CADJ = 0.00125f;

    float ldacc[2] = {0.f, 0.f};
    int cur = OFF_X0, nxt = OFF_X1;

    __syncthreads();

    for (int layer = 0; layer < LAYERS; layer++) {
        // ---- CTA-wide W1 stage: 128 rows x 64 cols ----
        const float* W1l = W1m + layer*WIDTH*DDIM;
        for (int i = tid; i < WIDTH*DDIM/4; i += NTHREADS) {
            int w = i >> 4, c4 = i & 15;
            float4 v = ((const float4*)W1l)[i];
            *(float4*)&sm[OFF_WS + w*WSPAD + c4*4] = v;
        }
        __syncthreads();

        // ---- GEMM1: warp w -> hidden 8w..8w+8; lane -> rows {lane, lane+32}
        {
            unsigned long long acc[2][8];
#pragma unroll
            for (int ri = 0; ri < 2; ri++)
#pragma unroll
                for (int p = 0; p < 8; p++) acc[ri][p] = 0ull;

            const float* wsp = &sm[OFF_WS + (warpi*8)*WSPAD];
            const int kb = warpi + 1;       // k4 iterations (prefix of octet)
#pragma unroll 4
            for (int k4 = 0; k4 < kb; k4++) {
                ulonglong2 x0 = *(const ulonglong2*)&sm[cur + (lane     )*XPAD + k4*4];
                ulonglong2 x1 = *(const ulonglong2*)&sm[cur + (lane + 32)*XPAD + k4*4];
#pragma unroll
                for (int p = 0; p < 8; p++) {
                    ulonglong2 wv = *(const ulonglong2*)&wsp[p*WSPAD + k4*4];
                    acc[0][p] = ffma2(x0.x, wv.x, acc[0][p]);
                    acc[0][p] = ffma2(x0.y, wv.y, acc[0][p]);
                    acc[1][p] = ffma2(x1.x, wv.x, acc[1][p]);
                    acc[1][p] = ffma2(x1.y, wv.y, acc[1][p]);
                }
            }
            const float* bptr = &b1p[layer*WIDTH + warpi*8];
            float4 bv0 = *(const float4*)bptr;
            float4 bv1 = *(const float4*)(bptr + 4);
            float b[8] = {bv0.x, bv0.y, bv0.z, bv0.w, bv1.x, bv1.y, bv1.z, bv1.w};
#pragma unroll
            for (int ri = 0; ri < 2; ri++) {
                int r = lane + 32*ri;
                float hv[8];
#pragma unroll
                for (int p = 0; p < 8; p++) {
                    float2 u = unpack2(acc[ri][p]);
                    hv[p] = fmaxf(u.x + u.y + b[p], 0.f);
                }
                *(float4*)&sm[OFF_H + r*HPAD + warpi*8]     = make_float4(hv[0],hv[1],hv[2],hv[3]);
                *(float4*)&sm[OFF_H + r*HPAD + warpi*8 + 4] = make_float4(hv[4],hv[5],hv[6],hv[7]);
            }
        }
        __syncthreads();   // H ready

        // ---- GEMM2 + streamed spline over 4 chunks of 16 dims ----
        for (int chunk = 0; chunk < NCHUNK; chunk++) {
            const int d0 = chunk * DG;
            const int d  = d0 + dl;
            const int kmax   = kmax_of(d);              // warp-uniform
            const int chunkK = kmax_of(d0 + 15);        // CTA-uniform
            const float* Wol = Wom + layer*DDIM*PPD*WIDTH;
            const float* bo  = boutg + (layer*DDIM + d)*PPD;

            float pr[2][8];
            float st_xi[2], st_invdx[2], st_yk[2], st_dyv[2], st_sk[2];
            int   st_k[2];

            // ===== phase 1: widths -> bin index, xi, invdx =====
            gemm2_pass<0, 8>(sm, Wol, bo, d0, dl, lane, chunkK, kmax, pr);
#pragma unroll
            for (int ri = 0; ri < 2; ri++) {
                float mw = pr[ri][0];
#pragma unroll
                for (int j = 1; j < 8; j++) mw = fmaxf(mw, pr[ri][j]);
                float ew[8]; float swv = 0.f;
#pragma unroll
                for (int j = 0; j < 8; j++) { ew[j] = __expf(pr[ri][j] - mw); swv += ew[j]; }
                float isc = __frcp_rn(swv) * C1;     // fold C1 into scale
                float cadj = CADJ * C1;

                float xraw = sm[cur + (lane + 32*ri)*XPAD + d];
                float xc = fminf(fmaxf(xraw, -BI), BI);

                // running-update bin search: last j with xc >= left edge
                float xl = -BI;
                float xk = -BI, xk1 = -BI;
                int k = 0;
#pragma unroll
                for (int j = 0; j < 8; j++) {
                    float wj = ew[j]*isc + cadj;
                    float xr2 = xl + wj;
                    if (xc >= xl) { k = j; xk = xl; xk1 = xr2; }
                    xl = xr2;
                }
                float invdx = __frcp_rn(xk1 - xk);
                st_invdx[ri] = invdx;
                st_xi[ri] = (xc - xk) * invdx;
                st_k[ri] = k;
            }

            // ===== phase 2: heights -> yk, dyv, sk =====
            gemm2_pass<8, 8>(sm, Wol, bo, d0, dl, lane, chunkK, kmax, pr);
#pragma unroll
            for (int ri = 0; ri < 2; ri++) {
                float mh = pr[ri][0];
#pragma unroll
                for (int j = 1; j < 8; j++) mh = fmaxf(mh, pr[ri][j]);
                float eh[8]; float shv = 0.f;
#pragma unroll
                for (int j = 0; j < 8; j++) { eh[j] = __expf(pr[ri][j] - mh); shv += eh[j]; }
                float isc = __frcp_rn(shv) * C1;
                float cadj = CADJ * C1;

                const int k = st_k[ri];
                float yl = -BI;
                float yk = -BI, yk1 = -BI;
#pragma unroll
                for (int j = 0; j < 8; j++) {
                    float hj = eh[j]*isc + cadj;
                    float yr2 = yl + hj;
                    if (j == k) { yk = yl; yk1 = yr2; }
                    yl = yr2;
                }
                st_yk[ri] = yk;
                st_dyv[ri] = yk1 - yk;
                st_sk[ri] = st_dyv[ri] * st_invdx[ri];
            }

            // ===== phase 3: derivatives (only the 2 selected) -> finish =====
            gemm2_pass<16, 7>(sm, Wol, bo, d0, dl, lane, chunkK, kmax, pr);
#pragma unroll
            for (int ri = 0; ri < 2; ri++) {
                const int k = st_k[ri];
                // select raw params v_{k-1}, v_k (cheap FSELs)
                float vkm1 = 0.f, vk = 0.f;
#pragma unroll
                for (int j = 0; j < 7; j++) {
                    float v = pr[ri][j];
                    if (j == k - 1) vkm1 = v;
                    if (j == k)     vk   = v;
                }
                // softplus only where needed (2 MUFU each)
                float dk  = (k >= 1) ? (softplus_fast(vkm1) + 0.001f) : 1.f;
                float dk1 = (k <= 6) ? (softplus_fast(vk)   + 0.001f) : 1.f;

                float xi = st_xi[ri];
                float omx = 1.f - xi;
                float xiomx = xi * omx;
                float sk = st_sk[ri];
                float den = sk + (dk1 + dk - 2.f*sk) * xiomx;
                float invden = __frcp_rn(den);
                float nume = sk*xi*xi + dk*xiomx;
                float outv = st_yk[ri] + st_dyv[ri] * nume * invden;
                float ldn = dk1*xi*xi + 2.f*sk*xiomx + dk*omx*omx;
                // single-log logdet: log(sk^2 * ldn / den^2)
                float ld = __logf(sk*sk*ldn*(invden*invden));

                float xraw = sm[cur + (lane + 32*ri)*XPAD + d];
                bool inside = (xraw > -BI) && (xraw < BI);
                float xo2 = inside ? outv : xraw;
                sm[nxt + (lane + 32*ri)*XPAD + (DDIM-1 - d)] = xo2;  // reversal fused
                ldacc[ri] += inside ? ld : 0.f;
            }
        }

        __syncthreads();   // X(nxt) ready
        int t = cur; cur = nxt; nxt = t;
    }

    // ---- outputs: [xo (B*64) | ldf (B) | yo (B*64) | ldg (B)]
    const int xbase  = flow ? (BATCH*DDIM + BATCH) : 0;
    const int ldbase = flow ? (2*BATCH*DDIM + BATCH) : (BATCH*DDIM);

    for (int i = tid; i < TB*DDIM; i += NTHREADS) {
        int rr = i >> 6, dd = i & 63;
        out[xbase + row0*DDIM + i] = sm[cur + rr*XPAD + dd];
    }

    // log-det reduction: 16 dim-class partials per row
    float* red = &sm[OFF_WS];
#pragma unroll
    for (int ri = 0; ri < 2; ri++)
        red[(lane + 32*ri)*16 + dl] = ldacc[ri];
    __syncthreads();
    if (tid < TB) {
        float s = 0.f;
#pragma unroll
        for (int j = 0; j < 16; j++) s += red[tid*16 + j];
        out[ldbase + row0 + tid] = s;
    }
}

// ---------------------------------------------------------------------------
extern "C" void kernel_launch(void* const* d_in, const int* in_sizes, int n_in,
                              void* d_out, int out_size)
{
    const float* x      = (const float*)d_in[0];
    const float* y      = (const float*)d_in[1];
    const float* f_W1   = (const float*)d_in[2];
    const float* f_b1   = (const float*)d_in[3];
    const float* f_Wout = (const float*)d_in[4];
    const float* f_bout = (const float*)d_in[5];
    const float* g_W1   = (const float*)d_in[6];
    const float* g_b1   = (const float*)d_in[7];
    const float* g_Wout = (const float*)d_in[8];
    const float* g_bout = (const float*)d_in[9];
    float* out = (float*)d_out;

    cudaFuncSetAttribute(maf_kernel, cudaFuncAttributeMaxDynamicSharedMemorySize, SMEM_BYTES);

    prep_kernel<<<1024, 256>>>(f_W1, f_Wout, g_W1, g_Wout, f_b1, g_b1);

    dim3 grid(BATCH/TB, 2);
    maf_kernel<<<grid, NTHREADS, SMEM_BYTES>>>(x, y, f_bout, g_bout, out);
}

// round 11
// speedup vs baseline: 1.1328x; 1.0082x over previous
#include <cuda_runtime.h>

#define LAYERS   8
#define WIDTH    128
#define DDIM     64
#define KNOTS    8
#define PPD      23          // 3*KNOTS-1
#define BATCH    16384
#define TB       64          // batch rows per CTA
#define NTHREADS 512
#define DG       16          // dims per chunk (1 per warp)
#define NCHUNK   (DDIM/DG)   // 4
#define XPAD     68
#define HPAD     132
#define WQPAD    36          // 32-col quarter staging row stride
#define BUFSZ    (128*WQPAD) // one ping-pong buffer (128 rows)
#define BI       4.0f

// shared memory layout (float offsets)
#define OFF_X0   0
#define OFF_X1   (TB*XPAD)                    // 4352
#define OFF_H    (2*TB*XPAD)                  // 8704
#define OFF_WS   (2*TB*XPAD + TB*HPAD)        // 17152
#define SMEM_FLOATS (OFF_WS + 2*BUFSZ)        // 17152 + 9216 = 26368
#define SMEM_BYTES  (SMEM_FLOATS*4)           // 105472 B -> 2 CTAs/SM

// Pre-masked, degree-sorted weights (static device scratch).
// g_Wom padded +128: pass-3 staging reads one row past the logical end.
__device__ float g_W1m[2*LAYERS*WIDTH*DDIM];
__device__ float g_Wom[2*LAYERS*DDIM*PPD*WIDTH + 128];
__device__ float g_b1p[2*LAYERS*WIDTH];

// ---------------------------------------------------------------------------
// packed fp32x2 FMA: 2 MACs per fma-pipe issue slot
// ---------------------------------------------------------------------------
__device__ __forceinline__ unsigned long long ffma2(unsigned long long a,
                                                    unsigned long long b,
                                                    unsigned long long c)
{
    unsigned long long d;
    asm("fma.rn.f32x2 %0, %1, %2, %3;" : "=l"(d) : "l"(a), "l"(b), "l"(c));
    return d;
}
__device__ __forceinline__ float2 unpack2(unsigned long long v)
{
    float2 r;
    asm("mov.b64 {%0, %1}, %2;" : "=f"(r.x), "=f"(r.y) : "l"(v));
    return r;
}

// softplus = max(v,0) + log(1 + exp(-|v|))   (2 MUFU, no library tail)
__device__ __forceinline__ float softplus_fast(float v)
{
    float t = __expf(-fabsf(v));
    return fmaxf(v, 0.f) + __logf(1.f + t);
}

// ---------------------------------------------------------------------------
// Degree-sorted hidden permutation.
// ---------------------------------------------------------------------------
__host__ __device__ __forceinline__ int sdeg(int j) { return (j < 6) ? (j/3) : ((j-2)>>1); }
__host__ __device__ __forceinline__ int permf(int j)
{
    if (j < 3)  return (j == 0) ? 0 : (j == 1 ? 63 : 126);
    if (j < 6)  return (j == 3) ? 1 : (j == 4 ? 64 : 127);
    int v = (j - 2) >> 1;
    return ((j & 1) == 0) ? v : v + 63;
}
// prefix length of dim d over sorted hidden, rounded up to 8
__device__ __forceinline__ int kmax_of(int d)
{
    int n = (d == 0) ? 0 : (d == 1 ? 3 : 2*d + 2);
    n = (n + 7) & ~7;
    return n > 128 ? 128 : n;
}

// ---------------------------------------------------------------------------
// Prep: mask + permute weights once per launch.
// ---------------------------------------------------------------------------
__global__ void prep_kernel(const float* __restrict__ fW1, const float* __restrict__ fWo,
                            const float* __restrict__ gW1, const float* __restrict__ gWo,
                            const float* __restrict__ fb1, const float* __restrict__ gb1)
{
    const int N1 = LAYERS*WIDTH*DDIM;
    const int N2 = LAYERS*DDIM*PPD*WIDTH;
    const int stride = gridDim.x * blockDim.x;
    const int t0 = blockIdx.x*blockDim.x + threadIdx.x;

    for (int i = t0; i < 2*N1; i += stride) {
        int fl = i / N1, j = i - fl*N1;
        int row = (j >> 6) & (WIDTH-1);
        int c = j & (DDIM-1);
        int l = j >> 13;
        const float* s = fl ? gW1 : fW1;
        int src = permf(row);
        g_W1m[i] = (c <= sdeg(row)) ? s[l*WIDTH*DDIM + src*DDIM + c] : 0.f;
    }
    for (int i = t0; i < 2*N2; i += stride) {
        int fl = i / N2, j = i - fl*N2;
        int col = j & (WIDTH-1);
        int o = (j >> 7) % (DDIM*PPD);
        int l = j / (DDIM*PPD*WIDTH);
        int d = o / PPD;
        const float* s = fl ? gWo : fWo;
        int src = permf(col);
        g_Wom[i] = (sdeg(col) < d) ? s[l*(DDIM*PPD)*WIDTH + o*WIDTH + src] : 0.f;
    }
    if (t0 < 128) g_Wom[2*N2 + t0] = 0.f;   // pad tail
    for (int i = t0; i < 2*LAYERS*WIDTH; i += stride) {
        int fl = i / (LAYERS*WIDTH), j = i - fl*(LAYERS*WIDTH);
        int l = j >> 7, w = j & (WIDTH-1);
        const float* s = fl ? gb1 : fb1;
        g_b1p[i] = s[l*WIDTH + permf(w)];
    }
}

// ---------------------------------------------------------------------------
// GEMM2 quarter stage: 16 dims x 8 params x 32 cols of Wout -> buffer (q&1).
// ---------------------------------------------------------------------------
__device__ __forceinline__ void stage_q(
    float* sm, const float* __restrict__ Wol, int d0, int pbase, int q)
{
    float* buf = &sm[OFF_WS + (q & 1)*BUFSZ];
#pragma unroll
    for (int it = 0; it < 2; it++) {
        int i = threadIdx.x + it*NTHREADS;      // 1024 float4s
        int rr = i >> 3, c4 = i & 7;
        int dd = rr >> 3, pp = rr & 7;
        float4 v = *(const float4*)&Wol[((d0+dd)*PPD + pbase + pp)*WIDTH + q*32 + c4*4];
        *(float4*)&buf[rr*WQPAD + c4*4] = v;
    }
}

// ---------------------------------------------------------------------------
// GEMM2 pass: PCNT params x 2 rows over this warp's dim K-prefix.
// Quarter-grain ping-pong staging: each barrier interval = [compute q |
// stage q+1]; low-kmax warps do memory work while high-kmax warps FFMA.
// ---------------------------------------------------------------------------
template<int PBASE, int PCNT>
__device__ __forceinline__ void gemm2_pass(
    float* sm, const float* __restrict__ Wol, const float* __restrict__ bo,
    int d0, int dl, int lane, int nq, int kmax, float out[2][8])
{
    unsigned long long acc[2][PCNT];
#pragma unroll
    for (int ri = 0; ri < 2; ri++)
#pragma unroll
        for (int p = 0; p < PCNT; p++) acc[ri][p] = 0ull;

    stage_q(sm, Wol, d0, PBASE, 0);
    __syncthreads();

    for (int q = 0; q < nq; q++) {
        int bound = kmax - 32*q;                    // warp-uniform
        bound = bound < 0 ? 0 : (bound > 32 ? 32 : bound);
        const float* hbase = &sm[OFF_H + q*32];
        const float* wsp   = &sm[OFF_WS + (q & 1)*BUFSZ + (dl*8)*WQPAD];
#pragma unroll 4
        for (int k4 = 0; k4 < (bound >> 2); k4++) {
            ulonglong2 h0 = *(const ulonglong2*)&hbase[(lane     )*HPAD + k4*4];
            ulonglong2 h1 = *(const ulonglong2*)&hbase[(lane + 32)*HPAD + k4*4];
#pragma unroll
            for (int p = 0; p < PCNT; p++) {
                ulonglong2 wv = *(const ulonglong2*)&wsp[p*WQPAD + k4*4];
                acc[0][p] = ffma2(h0.x, wv.x, acc[0][p]);
                acc[0][p] = ffma2(h0.y, wv.y, acc[0][p]);
                acc[1][p] = ffma2(h1.x, wv.x, acc[1][p]);
                acc[1][p] = ffma2(h1.y, wv.y, acc[1][p]);
            }
        }
        if (q + 1 < nq) stage_q(sm, Wol, d0, PBASE, q + 1);
        __syncthreads();
    }

#pragma unroll
    for (int ri = 0; ri < 2; ri++)
#pragma unroll
        for (int p = 0; p < PCNT; p++) {
            float2 u = unpack2(acc[ri][p]);
            out[ri][p] = u.x + u.y + bo[PBASE + p];
        }
}

// ---------------------------------------------------------------------------
// Main kernel: one CTA (512 thr) = 64 rows through all 8 layers; 2 CTAs/SM.
// GEMM1 balanced: warp w owns hidden quads {w, 31-w} (uniform work).
// GEMM2: warp w owns dim d0+w; lane owns rows {lane, lane+32}.
// ---------------------------------------------------------------------------
__global__ __launch_bounds__(NTHREADS, 2)
void maf_kernel(const float* __restrict__ xin_f, const float* __restrict__ xin_g,
                const float* __restrict__ f_bout, const float* __restrict__ g_bout,
                float* __restrict__ out)
{
    extern __shared__ float sm[];
    const int tid   = threadIdx.x;
    const int flow  = blockIdx.y;
    const int row0  = blockIdx.x * TB;
    const int warpi = tid >> 5;    // 0..15
    const int lane  = tid & 31;
    const int dl    = warpi;       // dim lane within chunk

    const float* xin   = flow ? xin_g  : xin_f;
    const float* boutg = flow ? g_bout : f_bout;
    const float* b1p   = g_b1p + flow * (LAYERS*WIDTH);
    const float* W1m   = g_W1m + flow * (LAYERS*WIDTH*DDIM);
    const float* Wom   = g_Wom + flow * (LAYERS*DDIM*PPD*WIDTH);

    for (int i = tid; i < TB*DDIM; i += NTHREADS) {
        int r = i >> 6, d = i & 63;
        sm[OFF_X0 + r*XPAD + d] = xin[row0*DDIM + i];
    }

    const float C1 = 8.0f / 1.01f;
    const float CADJ = 0.00125f;

    float ldacc[2] = {0.f, 0.f};
    int cur = OFF_X0, nxt = OFF_X1;

    __syncthreads();

    for (int layer = 0; layer < LAYERS; layer++) {
        // ---- W1 stage: 128 rows x 64 cols, split into 2 x 32-col buffers
        const float* W1l = W1m + layer*WIDTH*DDIM;
#pragma unroll
        for (int it = 0; it < 4; it++) {
            int i = tid + it*NTHREADS;              // 2048 float4s
            int rr = i >> 4, c4 = i & 15;
            float4 v = *(const float4*)&W1l[rr*DDIM + c4*4];
            *(float4*)&sm[OFF_WS + (c4 >> 3)*BUFSZ + rr*WQPAD + (c4 & 7)*4] = v;
        }
        __syncthreads();

        // ---- GEMM1 (balanced): warp w -> quads {w, 31-w}; rows {lane,lane+32}
        {
            const int qa = warpi, qb = 31 - warpi;
            const int ka  = (qa + 2) >> 1;          // <= 8, all in buf0
            const int kb4 = (qb + 2) >> 1;          // 9..16, spans both bufs

            unsigned long long acc[2][8];           // [row][0-3 quadA, 4-7 quadB]
#pragma unroll
            for (int ri = 0; ri < 2; ri++)
#pragma unroll
                for (int p = 0; p < 8; p++) acc[ri][p] = 0ull;

            const float* wa  = &sm[OFF_WS + (4*qa)*WQPAD];          // buf0
            const float* wb0 = &sm[OFF_WS + (4*qb)*WQPAD];          // buf0
            const float* wb1 = &sm[OFF_WS + BUFSZ + (4*qb)*WQPAD];  // buf1

#pragma unroll 2
            for (int kk = 0; kk < ka; kk++) {
                ulonglong2 x0 = *(const ulonglong2*)&sm[cur + (lane     )*XPAD + kk*4];
                ulonglong2 x1 = *(const ulonglong2*)&sm[cur + (lane + 32)*XPAD + kk*4];
#pragma unroll
                for (int p = 0; p < 4; p++) {
                    ulonglong2 wv = *(const ulonglong2*)&wa[p*WQPAD + kk*4];
                    acc[0][p] = ffma2(x0.x, wv.x, acc[0][p]);
                    acc[0][p] = ffma2(x0.y, wv.y, acc[0][p]);
                    acc[1][p] = ffma2(x1.x, wv.x, acc[1][p]);
                    acc[1][p] = ffma2(x1.y, wv.y, acc[1][p]);
                }
            }
#pragma unroll 2
            for (int kk = 0; kk < 8; kk++) {
                ulonglong2 x0 = *(const ulonglong2*)&sm[cur + (lane     )*XPAD + kk*4];
                ulonglong2 x1 = *(const ulonglong2*)&sm[cur + (lane + 32)*XPAD + kk*4];
#pragma unroll
                for (int p = 0; p < 4; p++) {
                    ulonglong2 wv = *(const ulonglong2*)&wb0[p*WQPAD + kk*4];
                    acc[0][4+p] = ffma2(x0.x, wv.x, acc[0][4+p]);
                    acc[0][4+p] = ffma2(x0.y, wv.y, acc[0][4+p]);
                    acc[1][4+p] = ffma2(x1.x, wv.x, acc[1][4+p]);
                    acc[1][4+p] = ffma2(x1.y, wv.y, acc[1][4+p]);
                }
            }
#pragma unroll 2
            for (int kk = 8; kk < kb4; kk++) {
                int kl = kk - 8;
                ulonglong2 x0 = *(const ulonglong2*)&sm[cur + (lane     )*XPAD + kk*4];
                ulonglong2 x1 = *(const ulonglong2*)&sm[cur + (lane + 32)*XPAD + kk*4];
#pragma unroll
                for (int p = 0; p < 4; p++) {
                    ulonglong2 wv = *(const ulonglong2*)&wb1[p*WQPAD + kl*4];
                    acc[0][4+p] = ffma2(x0.x, wv.x, acc[0][4+p]);
                    acc[0][4+p] = ffma2(x0.y, wv.y, acc[0][4+p]);
                    acc[1][4+p] = ffma2(x1.x, wv.x, acc[1][4+p]);
                    acc[1][4+p] = ffma2(x1.y, wv.y, acc[1][4+p]);
                }
            }

            float4 ba = *(const float4*)&b1p[layer*WIDTH + 4*qa];
            float4 bb = *(const float4*)&b1p[layer*WIDTH + 4*qb];
            float bav[4] = {ba.x, ba.y, ba.z, ba.w};
            float bbv[4] = {bb.x, bb.y, bb.z, bb.w};
#pragma unroll
            for (int ri = 0; ri < 2; ri++) {
                int r = lane + 32*ri;
                float ha[4], hb[4];
#pragma unroll
                for (int p = 0; p < 4; p++) {
                    float2 ua = unpack2(acc[ri][p]);
                    ha[p] = fmaxf(ua.x + ua.y + bav[p], 0.f);
                    float2 ub = unpack2(acc[ri][4+p]);
                    hb[p] = fmaxf(ub.x + ub.y + bbv[p], 0.f);
                }
                *(float4*)&sm[OFF_H + r*HPAD + 4*qa] = make_float4(ha[0],ha[1],ha[2],ha[3]);
                *(float4*)&sm[OFF_H + r*HPAD + 4*qb] = make_float4(hb[0],hb[1],hb[2],hb[3]);
            }
        }
        __syncthreads();   // H ready

        // ---- GEMM2 + streamed spline over 4 chunks of 16 dims ----
        for (int chunk = 0; chunk < NCHUNK; chunk++) {
            const int d0 = chunk * DG;
            const int d  = d0 + dl;
            const int kmax = kmax_of(d);                // warp-uniform
            const int nq   = kmax_of(d0 + 15) >> 5;     // CTA-uniform (1..4)
            const float* Wol = Wom + layer*DDIM*PPD*WIDTH;
            const float* bo  = boutg + (layer*DDIM + d)*PPD;

            float pr[2][8];
            float st_xi[2], st_invdx[2], st_yk[2], st_dyv[2], st_sk[2];
            int   st_k[2];

            // ===== phase 1: widths -> bin index, xi, invdx =====
            gemm2_pass<0, 8>(sm, Wol, bo, d0, dl, lane, nq, kmax, pr);
#pragma unroll
            for (int ri = 0; ri < 2; ri++) {
                float mw = pr[ri][0];
#pragma unroll
                for (int j = 1; j < 8; j++) mw = fmaxf(mw, pr[ri][j]);
                float ew[8]; float swv = 0.f;
#pragma unroll
                for (int j = 0; j < 8; j++) { ew[j] = __expf(pr[ri][j] - mw); swv += ew[j]; }
                float isc = __frcp_rn(swv) * C1;
                float cadj = CADJ * C1;

                float xraw = sm[cur + (lane + 32*ri)*XPAD + d];
                float xc = fminf(fmaxf(xraw, -BI), BI);

                float xl = -BI;
                float xk = -BI, xk1 = -BI;
                int k = 0;
#pragma unroll
                for (int j = 0; j < 8; j++) {
                    float wj = ew[j]*isc + cadj;
                    float xr2 = xl + wj;
                    if (xc >= xl) { k = j; xk = xl; xk1 = xr2; }
                    xl = xr2;
                }
                float invdx = __frcp_rn(xk1 - xk);
                st_invdx[ri] = invdx;
                st_xi[ri] = (xc - xk) * invdx;
                st_k[ri] = k;
            }

            // ===== phase 2: heights -> yk, dyv, sk =====
            gemm2_pass<8, 8>(sm, Wol, bo, d0, dl, lane, nq, kmax, pr);
#pragma unroll
            for (int ri = 0; ri < 2; ri++) {
                float mh = pr[ri][0];
#pragma unroll
                for (int j = 1; j < 8; j++) mh = fmaxf(mh, pr[ri][j]);
                float eh[8]; float shv = 0.f;
#pragma unroll
                for (int j = 0; j < 8; j++) { eh[j] = __expf(pr[ri][j] - mh); shv += eh[j]; }
                float isc = __frcp_rn(shv) * C1;
                float cadj = CADJ * C1;

                const int k = st_k[ri];
                float yl = -BI;
                float yk = -BI, yk1 = -BI;
#pragma unroll
                for (int j = 0; j < 8; j++) {
                    float hj = eh[j]*isc + cadj;
                    float yr2 = yl + hj;
                    if (j == k) { yk = yl; yk1 = yr2; }
                    yl = yr2;
                }
                st_yk[ri] = yk;
                st_dyv[ri] = yk1 - yk;
                st_sk[ri] = st_dyv[ri] * st_invdx[ri];
            }

            // ===== phase 3: derivatives (only the 2 selected) -> finish =====
            gemm2_pass<16, 7>(sm, Wol, bo, d0, dl, lane, nq, kmax, pr);
#pragma unroll
            for (int ri = 0; ri < 2; ri++) {
                const int k = st_k[ri];
                float vkm1 = 0.f, vk = 0.f;
#pragma unroll
                for (int j = 0; j < 7; j++) {
                    float v = pr[ri][j];
                    if (j == k - 1) vkm1 = v;
                    if (j == k)     vk   = v;
                }
                float dk  = (k >= 1) ? (softplus_fast(vkm1) + 0.001f) : 1.f;
                float dk1 = (k <= 6) ? (softplus_fast(vk)   + 0.001f) : 1.f;

                float xi = st_xi[ri];
                float omx = 1.f - xi;
                float xiomx = xi * omx;
                float sk = st_sk[ri];
                float den = sk + (dk1 + dk - 2.f*sk) * xiomx;
                float invden = __frcp_rn(den);
                float nume = sk*xi*xi + dk*xiomx;
                float outv = st_yk[ri] + st_dyv[ri] * nume * invden;
                float ldn = dk1*xi*xi + 2.f*sk*xiomx + dk*omx*omx;
                float ld = __logf(sk*sk*ldn*(invden*invden));

                float xraw = sm[cur + (lane + 32*ri)*XPAD + d];
                bool inside = (xraw > -BI) && (xraw < BI);
                float xo2 = inside ? outv : xraw;
                sm[nxt + (lane + 32*ri)*XPAD + (DDIM-1 - d)] = xo2;  // reversal fused
                ldacc[ri] += inside ? ld : 0.f;
            }
        }

        __syncthreads();   // X(nxt) ready
        int t = cur; cur = nxt; nxt = t;
    }

    // ---- outputs: [xo (B*64) | ldf (B) | yo (B*64) | ldg (B)]
    const int xbase  = flow ? (BATCH*DDIM + BATCH) : 0;
    const int ldbase = flow ? (2*BATCH*DDIM + BATCH) : (BATCH*DDIM);

    for (int i = tid; i < TB*DDIM; i += NTHREADS) {
        int rr = i >> 6, dd = i & 63;
        out[xbase + row0*DDIM + i] = sm[cur + rr*XPAD + dd];
    }

    // log-det reduction: 16 dim-class partials per row
    float* red = &sm[OFF_WS];
#pragma unroll
    for (int ri = 0; ri < 2; ri++)
        red[(lane + 32*ri)*16 + dl] = ldacc[ri];
    __syncthreads();
    if (tid < TB) {
        float s = 0.f;
#pragma unroll
        for (int j = 0; j < 16; j++) s += red[tid*16 + j];
        out[ldbase + row0 + tid] = s;
    }
}

// ---------------------------------------------------------------------------
extern "C" void kernel_launch(void* const* d_in, const int* in_sizes, int n_in,
                              void* d_out, int out_size)
{
    const float* x      = (const float*)d_in[0];
    const float* y      = (const float*)d_in[1];
    const float* f_W1   = (const float*)d_in[2];
    const float* f_b1   = (const float*)d_in[3];
    const float* f_Wout = (const float*)d_in[4];
    const float* f_bout = (const float*)d_in[5];
    const float* g_W1   = (const float*)d_in[6];
    const float* g_b1   = (const float*)d_in[7];
    const float* g_Wout = (const float*)d_in[8];
    const float* g_bout = (const float*)d_in[9];
    float* out = (float*)d_out;

    cudaFuncSetAttribute(maf_kernel, cudaFuncAttributeMaxDynamicSharedMemorySize, SMEM_BYTES);

    prep_kernel<<<1024, 256>>>(f_W1, f_Wout, g_W1, g_Wout, f_b1, g_b1);

    dim3 grid(BATCH/TB, 2);
    maf_kernel<<<grid, NTHREADS, SMEM_BYTES>>>(x, y, f_bout, g_bout, out);
}